// round 2
// baseline (speedup 1.0000x reference)
#include <cuda_runtime.h>
#include <cstdint>

#define N_B 8
#define T_S 1024
#define D_IN 512
#define U_D 512
#define H_N 8
#define D_H 64

// Scratch for projected Q, K, V: [N, T, U] fp32, 16 MB each.
__device__ float g_Q[N_B * T_S * U_D];
__device__ float g_K[N_B * T_S * U_D];
__device__ float g_V[N_B * T_S * U_D];

// ---------------------------------------------------------------------------
// Helpers
// ---------------------------------------------------------------------------
__device__ __forceinline__ uint32_t f2tf32(float x) {
    uint32_t r;
    asm("cvt.rna.tf32.f32 %0, %1;" : "=r"(r) : "f"(x));
    return r;
}
__device__ __forceinline__ float f2tf32f(float x) { return __uint_as_float(f2tf32(x)); }

// D += A*B, m16n8k8 tf32. a[4], b[2] are tf32 bit patterns.
__device__ __forceinline__ void mma_tf32(float* d, const uint32_t* a, const uint32_t* b) {
    asm volatile(
        "mma.sync.aligned.m16n8k8.row.col.f32.tf32.tf32.f32 "
        "{%0,%1,%2,%3},{%4,%5,%6,%7},{%8,%9},{%0,%1,%2,%3};\n"
        : "+f"(d[0]), "+f"(d[1]), "+f"(d[2]), "+f"(d[3])
        : "r"(a[0]), "r"(a[1]), "r"(a[2]), "r"(a[3]), "r"(b[0]), "r"(b[1]));
}

__device__ __forceinline__ void cp_async16(float* s, const float* g) {
    uint32_t sa = (uint32_t)__cvta_generic_to_shared(s);
    asm volatile("cp.async.cg.shared.global [%0], [%1], 16;\n" :: "r"(sa), "l"(g));
}
__device__ __forceinline__ void cp_commit() { asm volatile("cp.async.commit_group;\n"); }
template <int N>
__device__ __forceinline__ void cp_wait() { asm volatile("cp.async.wait_group %0;\n" :: "n"(N)); }

// ---------------------------------------------------------------------------
// Projection GEMM: C[8192,512] = X[8192,512] @ W[512,512]
// blockIdx.z: 0 -> Q = query@Wq, 1 -> K = key@Wk, 2 -> V = key@Wv
// Tiles: BM=128, BN=64, BK=32, 256 threads (8 warps, 4x2 of 32x32 warp tiles)
// ---------------------------------------------------------------------------
#define GBM 128
#define GBN 64
#define GBK 32
#define A_LD 36
#define B_LD 68
#define SM_GEMM ((2 * GBM * A_LD + 2 * GBK * B_LD) * 4)

__global__ void __launch_bounds__(256) proj_gemm(
    const float* __restrict__ Xq, const float* __restrict__ Xk,
    const float* __restrict__ Wq, const float* __restrict__ Wk,
    const float* __restrict__ Wv) {
    const float* X;
    const float* W;
    float* C;
    if (blockIdx.z == 0) { X = Xq; W = Wq; C = g_Q; }
    else if (blockIdx.z == 1) { X = Xk; W = Wk; C = g_K; }
    else { X = Xk; W = Wv; C = g_V; }

    extern __shared__ float sm[];
    float* As = sm;                       // [2][GBM][A_LD]
    float* Bs = sm + 2 * GBM * A_LD;      // [2][GBK][B_LD]

    const int tid = threadIdx.x;
    const int m0 = blockIdx.x * GBM, n0 = blockIdx.y * GBN;
    const int ar = tid >> 3, ac = (tid & 7) * 4;     // A: 32 rows/step, 8 float4 per row
    const int br = tid >> 4, bc = (tid & 15) * 4;    // B: 16 rows/step, 16 float4 per row

    const int lane = tid & 31, wid = tid >> 5;
    const int g = lane >> 2, tg = lane & 3;
    const int wm = (wid & 3) * 32, wn = (wid >> 2) * 32;

    float acc[2][4][4];
#pragma unroll
    for (int mf = 0; mf < 2; mf++)
#pragma unroll
        for (int nf = 0; nf < 4; nf++)
#pragma unroll
            for (int i = 0; i < 4; i++) acc[mf][nf][i] = 0.f;

    const int NK = D_IN / GBK;  // 16

    // stage loader
    auto ldstage = [&](int buf, int kt) {
        const float* a_src = X + (size_t)(m0 + ar) * D_IN + kt * GBK + ac;
        float* a_dst = As + buf * GBM * A_LD + ar * A_LD + ac;
#pragma unroll
        for (int i = 0; i < 4; i++) cp_async16(a_dst + i * 32 * A_LD, a_src + (size_t)i * 32 * D_IN);
        const float* b_src = W + (size_t)(kt * GBK + br) * U_D + n0 + bc;
        float* b_dst = Bs + buf * GBK * B_LD + br * B_LD + bc;
#pragma unroll
        for (int i = 0; i < 2; i++) cp_async16(b_dst + i * 16 * B_LD, b_src + (size_t)i * 16 * U_D);
    };

    ldstage(0, 0);
    cp_commit();

    for (int kt = 0; kt < NK; ++kt) {
        if (kt + 1 < NK) {
            ldstage((kt + 1) & 1, kt + 1);
            cp_commit();
            cp_wait<1>();
        } else {
            cp_wait<0>();
        }
        __syncthreads();

        const float* Ab = As + (kt & 1) * GBM * A_LD;
        const float* Bb = Bs + (kt & 1) * GBK * B_LD;

#pragma unroll
        for (int kk = 0; kk < 4; kk++) {
            uint32_t a[2][4];
#pragma unroll
            for (int mf = 0; mf < 2; mf++) {
                const int rb = wm + mf * 16;
                a[mf][0] = f2tf32(Ab[(rb + g) * A_LD + kk * 8 + tg]);
                a[mf][1] = f2tf32(Ab[(rb + g + 8) * A_LD + kk * 8 + tg]);
                a[mf][2] = f2tf32(Ab[(rb + g) * A_LD + kk * 8 + tg + 4]);
                a[mf][3] = f2tf32(Ab[(rb + g + 8) * A_LD + kk * 8 + tg + 4]);
            }
            uint32_t b[4][2];
#pragma unroll
            for (int nf = 0; nf < 4; nf++) {
                b[nf][0] = f2tf32(Bb[(kk * 8 + tg) * B_LD + wn + nf * 8 + g]);
                b[nf][1] = f2tf32(Bb[(kk * 8 + tg + 4) * B_LD + wn + nf * 8 + g]);
            }
#pragma unroll
            for (int mf = 0; mf < 2; mf++)
#pragma unroll
                for (int nf = 0; nf < 4; nf++) mma_tf32(acc[mf][nf], a[mf], b[nf]);
        }
        __syncthreads();
    }

    // epilogue
#pragma unroll
    for (int mf = 0; mf < 2; mf++) {
        const int r0 = m0 + wm + mf * 16 + g;
#pragma unroll
        for (int nf = 0; nf < 4; nf++) {
            const int c = n0 + wn + nf * 8 + 2 * tg;
            *(float2*)(C + (size_t)r0 * U_D + c) = make_float2(acc[mf][nf][0], acc[mf][nf][1]);
            *(float2*)(C + (size_t)(r0 + 8) * U_D + c) = make_float2(acc[mf][nf][2], acc[mf][nf][3]);
        }
    }
}

// ---------------------------------------------------------------------------
// Flash attention: CTA = (q-tile of 64, head, batch). 128 threads, 4 warps,
// each warp owns 16 query rows. K/V tiles 64x64, online softmax in fp32.
// ---------------------------------------------------------------------------
#define Q_LD 68
#define V_LD 72
#define SM_ATTN ((3 * 64 * Q_LD + 64 * V_LD + 64) * 4)

__global__ void __launch_bounds__(128) attn_kernel(const int* __restrict__ mask,
                                                   float* __restrict__ out) {
    extern __shared__ float sm[];
    float* Qs = sm;                    // [64][Q_LD] (scale folded, tf32)
    float* Ks = Qs + 64 * Q_LD;        // [64][Q_LD] (tf32)
    float* Ps = Ks + 64 * Q_LD;        // [64][Q_LD] (tf32)
    float* Vs = Ps + 64 * Q_LD;        // [64][V_LD] (tf32)
    float* Msk = Vs + 64 * V_LD;       // [64] 1.0 = masked-out

    const int tid = threadIdx.x, lane = tid & 31, wid = tid >> 5;
    const int g = lane >> 2, tg = lane & 3;
    const int q0 = blockIdx.x * 64;
    const int h = blockIdx.y, n = blockIdx.z;
    const int wrow = wid * 16;
    const float scale = 0.04419417382415922f;  // 1/sqrt(512)

    const int lr = tid >> 4, lc = (tid & 15) * 4;

    // Load Q tile once (fold scale, convert tf32)
#pragma unroll
    for (int i = 0; i < 8; i++) {
        const int r = lr + i * 8;
        const float4 v = *(const float4*)(g_Q + (size_t)(n * T_S + q0 + r) * U_D + h * D_H + lc);
        float4 o;
        o.x = f2tf32f(v.x * scale);
        o.y = f2tf32f(v.y * scale);
        o.z = f2tf32f(v.z * scale);
        o.w = f2tf32f(v.w * scale);
        *(float4*)(Qs + r * Q_LD + lc) = o;
    }

    float m0 = -1e30f, m1 = -1e30f, l0 = 0.f, l1 = 0.f;
    float of[8][4];
#pragma unroll
    for (int nf = 0; nf < 8; nf++)
#pragma unroll
        for (int i = 0; i < 4; i++) of[nf][i] = 0.f;

    for (int kt = 0; kt < 16; kt++) {
        __syncthreads();  // protect K/V/mask reuse (and Q store on kt=0)
        const int j0 = kt * 64;
#pragma unroll
        for (int i = 0; i < 8; i++) {
            const int r = lr + i * 8;
            const float4 kv = *(const float4*)(g_K + (size_t)(n * T_S + j0 + r) * U_D + h * D_H + lc);
            float4 ok;
            ok.x = f2tf32f(kv.x); ok.y = f2tf32f(kv.y); ok.z = f2tf32f(kv.z); ok.w = f2tf32f(kv.w);
            *(float4*)(Ks + r * Q_LD + lc) = ok;
            const float4 vv = *(const float4*)(g_V + (size_t)(n * T_S + j0 + r) * U_D + h * D_H + lc);
            float4 ov;
            ov.x = f2tf32f(vv.x); ov.y = f2tf32f(vv.y); ov.z = f2tf32f(vv.z); ov.w = f2tf32f(vv.w);
            *(float4*)(Vs + r * V_LD + lc) = ov;
        }
        if (tid < 64) Msk[tid] = (mask[n * T_S + j0 + tid] != 0) ? 0.f : 1.f;
        __syncthreads();

        // --- S = Qs @ Ks^T (scale pre-folded) ---
        float sf[8][4];
#pragma unroll
        for (int nf = 0; nf < 8; nf++)
#pragma unroll
            for (int i = 0; i < 4; i++) sf[nf][i] = 0.f;

#pragma unroll
        for (int kk = 0; kk < 8; kk++) {
            uint32_t a[4];
            a[0] = __float_as_uint(Qs[(wrow + g) * Q_LD + kk * 8 + tg]);
            a[1] = __float_as_uint(Qs[(wrow + g + 8) * Q_LD + kk * 8 + tg]);
            a[2] = __float_as_uint(Qs[(wrow + g) * Q_LD + kk * 8 + tg + 4]);
            a[3] = __float_as_uint(Qs[(wrow + g + 8) * Q_LD + kk * 8 + tg + 4]);
#pragma unroll
            for (int nf = 0; nf < 8; nf++) {
                uint32_t b[2];
                b[0] = __float_as_uint(Ks[(nf * 8 + g) * Q_LD + kk * 8 + tg]);
                b[1] = __float_as_uint(Ks[(nf * 8 + g) * Q_LD + kk * 8 + tg + 4]);
                mma_tf32(sf[nf], a, b);
            }
        }

        // --- mask (reproduce jnp.where(mask, s, -1e6)) ---
#pragma unroll
        for (int nf = 0; nf < 8; nf++) {
            const float f0 = Msk[nf * 8 + 2 * tg];
            const float f1 = Msk[nf * 8 + 2 * tg + 1];
            if (f0 != 0.f) { sf[nf][0] = -1e6f; sf[nf][2] = -1e6f; }
            if (f1 != 0.f) { sf[nf][1] = -1e6f; sf[nf][3] = -1e6f; }
        }

        // --- online softmax ---
        float rm0 = -1e30f, rm1 = -1e30f;
#pragma unroll
        for (int nf = 0; nf < 8; nf++) {
            rm0 = fmaxf(rm0, fmaxf(sf[nf][0], sf[nf][1]));
            rm1 = fmaxf(rm1, fmaxf(sf[nf][2], sf[nf][3]));
        }
        rm0 = fmaxf(rm0, __shfl_xor_sync(0xffffffffu, rm0, 1));
        rm0 = fmaxf(rm0, __shfl_xor_sync(0xffffffffu, rm0, 2));
        rm1 = fmaxf(rm1, __shfl_xor_sync(0xffffffffu, rm1, 1));
        rm1 = fmaxf(rm1, __shfl_xor_sync(0xffffffffu, rm1, 2));

        const float mn0 = fmaxf(m0, rm0), mn1 = fmaxf(m1, rm1);
        const float al0 = __expf(m0 - mn0), al1 = __expf(m1 - mn1);
        float rs0 = 0.f, rs1 = 0.f;
#pragma unroll
        for (int nf = 0; nf < 8; nf++) {
            sf[nf][0] = __expf(sf[nf][0] - mn0);
            sf[nf][1] = __expf(sf[nf][1] - mn0);
            sf[nf][2] = __expf(sf[nf][2] - mn1);
            sf[nf][3] = __expf(sf[nf][3] - mn1);
            rs0 += sf[nf][0] + sf[nf][1];
            rs1 += sf[nf][2] + sf[nf][3];
        }
        rs0 += __shfl_xor_sync(0xffffffffu, rs0, 1);
        rs0 += __shfl_xor_sync(0xffffffffu, rs0, 2);
        rs1 += __shfl_xor_sync(0xffffffffu, rs1, 1);
        rs1 += __shfl_xor_sync(0xffffffffu, rs1, 2);

        l0 = l0 * al0 + rs0;
        l1 = l1 * al1 + rs1;
        m0 = mn0;
        m1 = mn1;

#pragma unroll
        for (int nf = 0; nf < 8; nf++) {
            of[nf][0] *= al0;
            of[nf][1] *= al0;
            of[nf][2] *= al1;
            of[nf][3] *= al1;
        }

        // --- P -> smem (tf32), warp-private rows ---
        __syncwarp();
#pragma unroll
        for (int nf = 0; nf < 8; nf++) {
            *(float2*)(Ps + (wrow + g) * Q_LD + nf * 8 + 2 * tg) =
                make_float2(f2tf32f(sf[nf][0]), f2tf32f(sf[nf][1]));
            *(float2*)(Ps + (wrow + g + 8) * Q_LD + nf * 8 + 2 * tg) =
                make_float2(f2tf32f(sf[nf][2]), f2tf32f(sf[nf][3]));
        }
        __syncwarp();

        // --- O += P @ V ---
#pragma unroll
        for (int kk = 0; kk < 8; kk++) {
            uint32_t a[4];
            a[0] = __float_as_uint(Ps[(wrow + g) * Q_LD + kk * 8 + tg]);
            a[1] = __float_as_uint(Ps[(wrow + g + 8) * Q_LD + kk * 8 + tg]);
            a[2] = __float_as_uint(Ps[(wrow + g) * Q_LD + kk * 8 + tg + 4]);
            a[3] = __float_as_uint(Ps[(wrow + g + 8) * Q_LD + kk * 8 + tg + 4]);
#pragma unroll
            for (int nf = 0; nf < 8; nf++) {
                uint32_t b[2];
                b[0] = __float_as_uint(Vs[(kk * 8 + tg) * V_LD + nf * 8 + g]);
                b[1] = __float_as_uint(Vs[(kk * 8 + tg + 4) * V_LD + nf * 8 + g]);
                mma_tf32(of[nf], a, b);
            }
        }
    }

    // --- epilogue: normalize and write [n, q, h*64 + d] ---
    const float il0 = 1.f / l0, il1 = 1.f / l1;
#pragma unroll
    for (int nf = 0; nf < 8; nf++) {
        const int c = h * D_H + nf * 8 + 2 * tg;
        *(float2*)(out + (size_t)(n * T_S + q0 + wrow + g) * U_D + c) =
            make_float2(of[nf][0] * il0, of[nf][1] * il0);
        *(float2*)(out + (size_t)(n * T_S + q0 + wrow + g + 8) * U_D + c) =
            make_float2(of[nf][2] * il1, of[nf][3] * il1);
    }
}

// ---------------------------------------------------------------------------
// Launch
// ---------------------------------------------------------------------------
extern "C" void kernel_launch(void* const* d_in, const int* in_sizes, int n_in,
                              void* d_out, int out_size) {
    const float* q = (const float*)d_in[0];
    const float* k = (const float*)d_in[1];
    const int* mask = (const int*)d_in[2];
    const float* Wq = (const float*)d_in[3];
    const float* Wk = (const float*)d_in[4];
    const float* Wv = (const float*)d_in[5];
    float* out = (float*)d_out;

    cudaFuncSetAttribute(proj_gemm, cudaFuncAttributeMaxDynamicSharedMemorySize, SM_GEMM);
    cudaFuncSetAttribute(attn_kernel, cudaFuncAttributeMaxDynamicSharedMemorySize, SM_ATTN);

    // Projections: z = {Q, K, V}. grid.x = 8192 rows / 128 = 64 tiles.
    proj_gemm<<<dim3((N_B * T_S) / GBM, U_D / GBN, 3), 256, SM_GEMM>>>(q, k, Wq, Wk, Wv);

    // Attention: x-fastest over q-tiles keeps each (h,n) K/V slice L2-resident
    attn_kernel<<<dim3(T_S / 64, H_N, N_B), 128, SM_ATTN>>>(mask, out);
}

// round 3
// speedup vs baseline: 1.0855x; 1.0855x over previous
#include <cuda_runtime.h>
#include <cstdint>

#define N_B 8
#define T_S 1024
#define D_IN 512
#define U_D 512
#define H_N 8
#define D_H 64

// Scratch for projected Q, K, V: [N, T, U] fp32, 16 MB each.
__device__ float g_Q[N_B * T_S * U_D];
__device__ float g_K[N_B * T_S * U_D];
__device__ float g_V[N_B * T_S * U_D];

// ---------------------------------------------------------------------------
// Helpers
// ---------------------------------------------------------------------------
__device__ __forceinline__ uint32_t f2tf32(float x) {
    uint32_t r;
    asm("cvt.rna.tf32.f32 %0, %1;" : "=r"(r) : "f"(x));
    return r;
}
__device__ __forceinline__ float f2tf32f(float x) { return __uint_as_float(f2tf32(x)); }

// D += A*B, m16n8k8 tf32. a[4], b[2] are tf32 bit patterns.
__device__ __forceinline__ void mma_tf32(float* d, const uint32_t* a, const uint32_t* b) {
    asm volatile(
        "mma.sync.aligned.m16n8k8.row.col.f32.tf32.tf32.f32 "
        "{%0,%1,%2,%3},{%4,%5,%6,%7},{%8,%9},{%0,%1,%2,%3};\n"
        : "+f"(d[0]), "+f"(d[1]), "+f"(d[2]), "+f"(d[3])
        : "r"(a[0]), "r"(a[1]), "r"(a[2]), "r"(a[3]), "r"(b[0]), "r"(b[1]));
}

// ldmatrix x4: 4 8x8 b16 matrices -> 4 regs. For 32-bit data each lane gets
// element (row = lane>>2, col32 = lane&3) of matrix j in reg j.
__device__ __forceinline__ void ldsm4(uint32_t& r0, uint32_t& r1, uint32_t& r2, uint32_t& r3,
                                      uint32_t addr) {
    asm volatile("ldmatrix.sync.aligned.m8n8.x4.shared.b16 {%0,%1,%2,%3}, [%4];"
                 : "=r"(r0), "=r"(r1), "=r"(r2), "=r"(r3)
                 : "r"(addr));
}

__device__ __forceinline__ void cp_async16(float* s, const float* g) {
    uint32_t sa = (uint32_t)__cvta_generic_to_shared(s);
    asm volatile("cp.async.cg.shared.global [%0], [%1], 16;\n" :: "r"(sa), "l"(g));
}
__device__ __forceinline__ void cp_commit() { asm volatile("cp.async.commit_group;\n"); }
template <int N>
__device__ __forceinline__ void cp_wait() { asm volatile("cp.async.wait_group %0;\n" :: "n"(N)); }

// ---------------------------------------------------------------------------
// Projection GEMM: C[8192,512] = X[8192,512] @ W[512,512]  (unchanged)
// ---------------------------------------------------------------------------
#define GBM 128
#define GBN 64
#define GBK 32
#define A_LD 36
#define B_LD 68
#define SM_GEMM ((2 * GBM * A_LD + 2 * GBK * B_LD) * 4)

__global__ void __launch_bounds__(256) proj_gemm(
    const float* __restrict__ Xq, const float* __restrict__ Xk,
    const float* __restrict__ Wq, const float* __restrict__ Wk,
    const float* __restrict__ Wv) {
    const float* X;
    const float* W;
    float* C;
    if (blockIdx.z == 0) { X = Xq; W = Wq; C = g_Q; }
    else if (blockIdx.z == 1) { X = Xk; W = Wk; C = g_K; }
    else { X = Xk; W = Wv; C = g_V; }

    extern __shared__ float sm[];
    float* As = sm;
    float* Bs = sm + 2 * GBM * A_LD;

    const int tid = threadIdx.x;
    const int m0 = blockIdx.x * GBM, n0 = blockIdx.y * GBN;
    const int ar = tid >> 3, ac = (tid & 7) * 4;
    const int br = tid >> 4, bc = (tid & 15) * 4;

    const int lane = tid & 31, wid = tid >> 5;
    const int g = lane >> 2, tg = lane & 3;
    const int wm = (wid & 3) * 32, wn = (wid >> 2) * 32;

    float acc[2][4][4];
#pragma unroll
    for (int mf = 0; mf < 2; mf++)
#pragma unroll
        for (int nf = 0; nf < 4; nf++)
#pragma unroll
            for (int i = 0; i < 4; i++) acc[mf][nf][i] = 0.f;

    const int NK = D_IN / GBK;

    auto ldstage = [&](int buf, int kt) {
        const float* a_src = X + (size_t)(m0 + ar) * D_IN + kt * GBK + ac;
        float* a_dst = As + buf * GBM * A_LD + ar * A_LD + ac;
#pragma unroll
        for (int i = 0; i < 4; i++) cp_async16(a_dst + i * 32 * A_LD, a_src + (size_t)i * 32 * D_IN);
        const float* b_src = W + (size_t)(kt * GBK + br) * U_D + n0 + bc;
        float* b_dst = Bs + buf * GBK * B_LD + br * B_LD + bc;
#pragma unroll
        for (int i = 0; i < 2; i++) cp_async16(b_dst + i * 16 * B_LD, b_src + (size_t)i * 16 * U_D);
    };

    ldstage(0, 0);
    cp_commit();

    for (int kt = 0; kt < NK; ++kt) {
        if (kt + 1 < NK) {
            ldstage((kt + 1) & 1, kt + 1);
            cp_commit();
            cp_wait<1>();
        } else {
            cp_wait<0>();
        }
        __syncthreads();

        const float* Ab = As + (kt & 1) * GBM * A_LD;
        const float* Bb = Bs + (kt & 1) * GBK * B_LD;

#pragma unroll
        for (int kk = 0; kk < 4; kk++) {
            uint32_t a[2][4];
#pragma unroll
            for (int mf = 0; mf < 2; mf++) {
                const int rb = wm + mf * 16;
                a[mf][0] = f2tf32(Ab[(rb + g) * A_LD + kk * 8 + tg]);
                a[mf][1] = f2tf32(Ab[(rb + g + 8) * A_LD + kk * 8 + tg]);
                a[mf][2] = f2tf32(Ab[(rb + g) * A_LD + kk * 8 + tg + 4]);
                a[mf][3] = f2tf32(Ab[(rb + g + 8) * A_LD + kk * 8 + tg + 4]);
            }
            uint32_t b[4][2];
#pragma unroll
            for (int nf = 0; nf < 4; nf++) {
                b[nf][0] = f2tf32(Bb[(kk * 8 + tg) * B_LD + wn + nf * 8 + g]);
                b[nf][1] = f2tf32(Bb[(kk * 8 + tg + 4) * B_LD + wn + nf * 8 + g]);
            }
#pragma unroll
            for (int mf = 0; mf < 2; mf++)
#pragma unroll
                for (int nf = 0; nf < 4; nf++) mma_tf32(acc[mf][nf], a[mf], b[nf]);
        }
        __syncthreads();
    }

#pragma unroll
    for (int mf = 0; mf < 2; mf++) {
        const int r0 = m0 + wm + mf * 16 + g;
#pragma unroll
        for (int nf = 0; nf < 4; nf++) {
            const int c = n0 + wn + nf * 8 + 2 * tg;
            *(float2*)(C + (size_t)r0 * U_D + c) = make_float2(acc[mf][nf][0], acc[mf][nf][1]);
            *(float2*)(C + (size_t)(r0 + 8) * U_D + c) = make_float2(acc[mf][nf][2], acc[mf][nf][3]);
        }
    }
}

// ---------------------------------------------------------------------------
// Flash attention v2: CTA = (q-tile 128, head, batch), 128 threads, 4 warps.
// Warp owns 32 q-rows (2 m-frags) -> each K/V fragment read feeds 2 mmas.
// Q/K/P fragments via ldmatrix.x4; V scalar conflict-free (LD=72).
// ---------------------------------------------------------------------------
#define QT 128
#define AL 68     // LD for Qs/Ks/Ps
#define VL 72     // LD for Vs (8*tg+g hits all 32 banks)
#define SM_ATTN ((QT * AL + 64 * AL + 64 * VL + QT * AL + 64) * 4)

__global__ void __launch_bounds__(128) attn_kernel(const int* __restrict__ mask,
                                                   float* __restrict__ out) {
    extern __shared__ float sm[];
    float* Qs = sm;                       // [128][AL] tf32, scale folded
    float* Ks = Qs + QT * AL;             // [64][AL]  tf32
    float* Vs = Ks + 64 * AL;             // [64][VL]  tf32
    float* Ps = Vs + 64 * VL;             // [128][AL] tf32
    float* Msk = Ps + QT * AL;            // [64] 1.0 = masked-out

    const int tid = threadIdx.x, lane = tid & 31, wid = tid >> 5;
    const int g = lane >> 2, tg = lane & 3;
    const int q0 = blockIdx.x * QT;
    const int h = blockIdx.y, n = blockIdx.z;
    const int wrow = wid * 32;
    const float scale = 0.04419417382415922f;  // 1/sqrt(512)

    const uint32_t sQ = (uint32_t)__cvta_generic_to_shared(Qs);
    const uint32_t sK = (uint32_t)__cvta_generic_to_shared(Ks);
    const uint32_t sP = (uint32_t)__cvta_generic_to_shared(Ps);

    // ldmatrix per-lane offsets (in floats)
    const int li = lane & 7, lj = lane >> 3;
    const int aoff = (li + (lj & 1) * 8) * AL + (lj >> 1) * 4;  // 16x8 A-frag pattern
    const int boff = (li + (lj >> 1) * 8) * AL + (lj & 1) * 4;  // 2x(8keys x 8cols) B pattern

    const int lr = tid >> 4;   // 0..7
    const int fc = tid & 15;   // float4 column

    // ---- Q prologue: 128x64, fold scale, cvt tf32 ----
#pragma unroll
    for (int i = 0; i < 16; i++) {
        const int r = lr + i * 8;
        const float4 v = *(const float4*)(g_Q + (size_t)(n * T_S + q0 + r) * U_D + h * D_H + fc * 4);
        float4 o;
        o.x = f2tf32f(v.x * scale); o.y = f2tf32f(v.y * scale);
        o.z = f2tf32f(v.z * scale); o.w = f2tf32f(v.w * scale);
        *(float4*)(Qs + r * AL + fc * 4) = o;
    }

    float mr[2][2], lr_[2][2];
#pragma unroll
    for (int mf = 0; mf < 2; mf++) { mr[mf][0] = mr[mf][1] = -1e30f; lr_[mf][0] = lr_[mf][1] = 0.f; }
    float of[2][8][4];
#pragma unroll
    for (int mf = 0; mf < 2; mf++)
#pragma unroll
        for (int nf = 0; nf < 8; nf++)
#pragma unroll
            for (int i = 0; i < 4; i++) of[mf][nf][i] = 0.f;

    for (int kt = 0; kt < 16; kt++) {
        __syncthreads();  // protect prior-tile K/V/Msk (and Q store on kt=0)
        const int j0 = kt * 64;
#pragma unroll
        for (int i = 0; i < 8; i++) {
            const int r = lr + i * 8;
            const size_t gb = (size_t)(n * T_S + j0 + r) * U_D + h * D_H + fc * 4;
            const float4 kv = *(const float4*)(g_K + gb);
            float4 ok;
            ok.x = f2tf32f(kv.x); ok.y = f2tf32f(kv.y); ok.z = f2tf32f(kv.z); ok.w = f2tf32f(kv.w);
            *(float4*)(Ks + r * AL + fc * 4) = ok;
            const float4 vv = *(const float4*)(g_V + gb);
            float4 ov;
            ov.x = f2tf32f(vv.x); ov.y = f2tf32f(vv.y); ov.z = f2tf32f(vv.z); ov.w = f2tf32f(vv.w);
            *(float4*)(Vs + r * VL + fc * 4) = ov;
        }
        if (tid < 64) Msk[tid] = (mask[n * T_S + j0 + tid] != 0) ? 0.f : 1.f;
        __syncthreads();

        // ---- S = Q @ K^T ----
        float sf[2][8][4];
#pragma unroll
        for (int mf = 0; mf < 2; mf++)
#pragma unroll
            for (int nf = 0; nf < 8; nf++)
#pragma unroll
                for (int i = 0; i < 4; i++) sf[mf][nf][i] = 0.f;

#pragma unroll
        for (int kk = 0; kk < 8; kk++) {
            uint32_t qa[2][4];
            ldsm4(qa[0][0], qa[0][1], qa[0][2], qa[0][3],
                  sQ + 4u * (uint32_t)(wrow * AL + kk * 8 + aoff));
            ldsm4(qa[1][0], qa[1][1], qa[1][2], qa[1][3],
                  sQ + 4u * (uint32_t)((wrow + 16) * AL + kk * 8 + aoff));
#pragma unroll
            for (int nfp = 0; nfp < 4; nfp++) {
                uint32_t kb[4];
                ldsm4(kb[0], kb[1], kb[2], kb[3],
                      sK + 4u * (uint32_t)(nfp * 16 * AL + kk * 8 + boff));
                mma_tf32(sf[0][2 * nfp], qa[0], kb);
                mma_tf32(sf[1][2 * nfp], qa[1], kb);
                mma_tf32(sf[0][2 * nfp + 1], qa[0], kb + 2);
                mma_tf32(sf[1][2 * nfp + 1], qa[1], kb + 2);
            }
        }

        // ---- mask (jnp.where(mask, s, -1e6)) ----
#pragma unroll
        for (int nf = 0; nf < 8; nf++) {
            const float f0 = Msk[nf * 8 + 2 * tg];
            const float f1 = Msk[nf * 8 + 2 * tg + 1];
#pragma unroll
            for (int mf = 0; mf < 2; mf++) {
                if (f0 != 0.f) { sf[mf][nf][0] = -1e6f; sf[mf][nf][2] = -1e6f; }
                if (f1 != 0.f) { sf[mf][nf][1] = -1e6f; sf[mf][nf][3] = -1e6f; }
            }
        }

        // ---- online softmax + P store (per m-frag) ----
#pragma unroll
        for (int mf = 0; mf < 2; mf++) {
            float rm0 = -1e30f, rm1 = -1e30f;
#pragma unroll
            for (int nf = 0; nf < 8; nf++) {
                rm0 = fmaxf(rm0, fmaxf(sf[mf][nf][0], sf[mf][nf][1]));
                rm1 = fmaxf(rm1, fmaxf(sf[mf][nf][2], sf[mf][nf][3]));
            }
            rm0 = fmaxf(rm0, __shfl_xor_sync(0xffffffffu, rm0, 1));
            rm0 = fmaxf(rm0, __shfl_xor_sync(0xffffffffu, rm0, 2));
            rm1 = fmaxf(rm1, __shfl_xor_sync(0xffffffffu, rm1, 1));
            rm1 = fmaxf(rm1, __shfl_xor_sync(0xffffffffu, rm1, 2));

            const float mn0 = fmaxf(mr[mf][0], rm0), mn1 = fmaxf(mr[mf][1], rm1);
            const float al0 = __expf(mr[mf][0] - mn0), al1 = __expf(mr[mf][1] - mn1);
            float rs0 = 0.f, rs1 = 0.f;
#pragma unroll
            for (int nf = 0; nf < 8; nf++) {
                sf[mf][nf][0] = __expf(sf[mf][nf][0] - mn0);
                sf[mf][nf][1] = __expf(sf[mf][nf][1] - mn0);
                sf[mf][nf][2] = __expf(sf[mf][nf][2] - mn1);
                sf[mf][nf][3] = __expf(sf[mf][nf][3] - mn1);
                rs0 += sf[mf][nf][0] + sf[mf][nf][1];
                rs1 += sf[mf][nf][2] + sf[mf][nf][3];
            }
            rs0 += __shfl_xor_sync(0xffffffffu, rs0, 1);
            rs0 += __shfl_xor_sync(0xffffffffu, rs0, 2);
            rs1 += __shfl_xor_sync(0xffffffffu, rs1, 1);
            rs1 += __shfl_xor_sync(0xffffffffu, rs1, 2);

            lr_[mf][0] = lr_[mf][0] * al0 + rs0;
            lr_[mf][1] = lr_[mf][1] * al1 + rs1;
            mr[mf][0] = mn0;
            mr[mf][1] = mn1;

#pragma unroll
            for (int nf = 0; nf < 8; nf++) {
                of[mf][nf][0] *= al0;
                of[mf][nf][1] *= al0;
                of[mf][nf][2] *= al1;
                of[mf][nf][3] *= al1;
            }

            const int pr = wrow + mf * 16;
#pragma unroll
            for (int nf = 0; nf < 8; nf++) {
                *(float2*)(Ps + (pr + g) * AL + nf * 8 + 2 * tg) =
                    make_float2(f2tf32f(sf[mf][nf][0]), f2tf32f(sf[mf][nf][1]));
                *(float2*)(Ps + (pr + g + 8) * AL + nf * 8 + 2 * tg) =
                    make_float2(f2tf32f(sf[mf][nf][2]), f2tf32f(sf[mf][nf][3]));
            }
        }
        __syncwarp();

        // ---- O += P @ V ----
#pragma unroll
        for (int kks = 0; kks < 8; kks++) {
            uint32_t pa[2][4];
            ldsm4(pa[0][0], pa[0][1], pa[0][2], pa[0][3],
                  sP + 4u * (uint32_t)(wrow * AL + kks * 8 + aoff));
            ldsm4(pa[1][0], pa[1][1], pa[1][2], pa[1][3],
                  sP + 4u * (uint32_t)((wrow + 16) * AL + kks * 8 + aoff));
#pragma unroll
            for (int nf = 0; nf < 8; nf++) {
                uint32_t vb[2];
                vb[0] = __float_as_uint(Vs[(kks * 8 + tg) * VL + nf * 8 + g]);
                vb[1] = __float_as_uint(Vs[(kks * 8 + tg + 4) * VL + nf * 8 + g]);
                mma_tf32(of[0][nf], pa[0], vb);
                mma_tf32(of[1][nf], pa[1], vb);
            }
        }
    }

    // ---- epilogue ----
#pragma unroll
    for (int mf = 0; mf < 2; mf++) {
        const float il0 = 1.f / lr_[mf][0], il1 = 1.f / lr_[mf][1];
        const int r0 = q0 + wrow + mf * 16 + g;
#pragma unroll
        for (int nf = 0; nf < 8; nf++) {
            const int c = h * D_H + nf * 8 + 2 * tg;
            *(float2*)(out + (size_t)(n * T_S + r0) * U_D + c) =
                make_float2(of[mf][nf][0] * il0, of[mf][nf][1] * il0);
            *(float2*)(out + (size_t)(n * T_S + r0 + 8) * U_D + c) =
                make_float2(of[mf][nf][2] * il1, of[mf][nf][3] * il1);
        }
    }
}

// ---------------------------------------------------------------------------
// Launch
// ---------------------------------------------------------------------------
extern "C" void kernel_launch(void* const* d_in, const int* in_sizes, int n_in,
                              void* d_out, int out_size) {
    const float* q = (const float*)d_in[0];
    const float* k = (const float*)d_in[1];
    const int* mask = (const int*)d_in[2];
    const float* Wq = (const float*)d_in[3];
    const float* Wk = (const float*)d_in[4];
    const float* Wv = (const float*)d_in[5];
    float* out = (float*)d_out;

    cudaFuncSetAttribute(proj_gemm, cudaFuncAttributeMaxDynamicSharedMemorySize, SM_GEMM);
    cudaFuncSetAttribute(attn_kernel, cudaFuncAttributeMaxDynamicSharedMemorySize, SM_ATTN);

    proj_gemm<<<dim3((N_B * T_S) / GBM, U_D / GBN, 3), 256, SM_GEMM>>>(q, k, Wq, Wk, Wv);

    // q-tiles x-fastest: 8 CTAs per (h,n) share the K/V slice in L2
    attn_kernel<<<dim3(T_S / QT, H_N, N_B), 128, SM_ATTN>>>(mask, out);
}